// round 3
// baseline (speedup 1.0000x reference)
#include <cuda_runtime.h>
#include <cuda_fp16.h>
#include <cuda_bf16.h>
#include <mma.h>
#include <cstdint>

using namespace nvcuda;

// Problem constants
constexpr int IN_F    = 4096;            // K
constexpr int OUT_F   = 4096;            // N
constexpr int M_TOTAL = 4 * 2048;        // M = 8192

// GEMM tiling (all smem strides multiples of 16 halfs = 32B)
constexpr int BM = 128, BN = 128, BK = 32;
constexpr int LDA_S = 48;    // halfs
constexpr int LDB_S = 144;   // halfs
constexpr int LDC_S = 136;   // floats

// Scratch (__device__ globals = allowed scratch)
__device__ __half g_W[(size_t)IN_F * OUT_F];     // dequantized weights (32MB)
__device__ __half g_X[(size_t)M_TOTAL * IN_F];   // canonical fp16 x (64MB)
__device__ int    g_mode;                        // 0 = f32, 1 = fp16, 2 = bf16

__device__ __forceinline__ float dec_h(unsigned short v) {
    __half_raw h; h.x = v; return __half2float(__half(h));
}
__device__ __forceinline__ float dec_b(unsigned short v) {
    __nv_bfloat16_raw r; r.x = v; return __bfloat162float(__nv_bfloat16(r));
}
__device__ __forceinline__ unsigned short enc_h(float f) {
    __half h = __float2half(f); return reinterpret_cast<unsigned short&>(h);
}
__device__ __forceinline__ unsigned short enc_b(float f) {
    __nv_bfloat16 b = __float2bfloat16(f); return reinterpret_cast<unsigned short&>(b);
}

// ---------------------------------------------------------------------------
// Kernel 0: dtype probe on scales (true values in (0.001, 0.011]).
//  - fp16 buffer: fp16-decode hits range for all 64 samples; others miss.
//  - bf16 buffer: bf16-decode hits for ALL 64 ushorts (and f32-read also hits,
//    since bf16 is truncated f32 -- so test bf16 BEFORE f32, needing >=48/64).
//  - f32 buffer : bf16-decode hits only the 32 high-halves (~32/64 < 48);
//    f32 read hits directly.
// ---------------------------------------------------------------------------
__global__ void detect_kernel(const void* scales) {
    const float*          sf = (const float*)scales;
    const unsigned short* su = (const unsigned short*)scales;
    int c16 = 0, cbf = 0;
    for (int i = 0; i < 64; i++) {
        float vh = dec_h(su[i]); if (vh > 0.0005f && vh < 0.02f) c16++;
        float vb = dec_b(su[i]); if (vb > 0.0005f && vb < 0.02f) cbf++;
    }
    (void)sf;
    g_mode = (c16 >= 48) ? 1 : ((cbf >= 48) ? 2 : 0);
}

// ---------------------------------------------------------------------------
// Kernel 1: canonicalize x -> fp16 g_X. 8 elements per thread.
//  mode 0: x is float32 (widened fp16; f32->fp16 recovers original bits)
//  mode 1: x is fp16 bits (copy)
//  mode 2: x is bf16 bits (convert)
// ---------------------------------------------------------------------------
__global__ void convert_x_kernel(const void* __restrict__ x_raw) {
    const int mode = g_mode;
    const size_t i8 = (size_t)blockIdx.x * blockDim.x + threadIdx.x; // 8-elt chunk
    __half out[8];
    if (mode == 0) {
        const float4* xf = (const float4*)x_raw;
        const float4 a = xf[i8 * 2 + 0];
        const float4 b = xf[i8 * 2 + 1];
        out[0] = __float2half(a.x); out[1] = __float2half(a.y);
        out[2] = __float2half(a.z); out[3] = __float2half(a.w);
        out[4] = __float2half(b.x); out[5] = __float2half(b.y);
        out[6] = __float2half(b.z); out[7] = __float2half(b.w);
    } else {
        const uint4 v = ((const uint4*)x_raw)[i8];
        const unsigned int w[4] = {v.x, v.y, v.z, v.w};
        if (mode == 1) {
            *reinterpret_cast<uint4*>(out) = v;
        } else {
#pragma unroll
            for (int k = 0; k < 4; k++) {
                out[2 * k + 0] = __float2half(dec_b((unsigned short)(w[k] & 0xFFFF)));
                out[2 * k + 1] = __float2half(dec_b((unsigned short)(w[k] >> 16)));
            }
        }
    }
    *reinterpret_cast<uint4*>(&g_X[i8 * 8]) = *reinterpret_cast<const uint4*>(out);
}

// ---------------------------------------------------------------------------
// Kernel 2: dequantize 4-bit weights -> fp16 W[K,N].
// One thread = one qweight word = 8 consecutive K-rows of column j.
//   W[i,j] = s[g,j] * (((qw[i/8,j] >> 4(i%8)) & 15) - ((qz[g,j/8] >> 4(j%8)) & 15))
// ---------------------------------------------------------------------------
__global__ void dequant_kernel(const int32_t* __restrict__ qweight,
                               const int32_t* __restrict__ qzeros,
                               const void* __restrict__ scales_raw) {
    const int mode = g_mode;
    const int j  = blockIdx.x * blockDim.x + threadIdx.x;   // 0..4095
    const int i8 = blockIdx.y;                               // 0..511
    const int g  = i8 >> 4;

    const uint32_t q = (uint32_t)qweight[(size_t)i8 * OUT_F + j];
    const int z = ((uint32_t)qzeros[(size_t)g * (OUT_F >> 3) + (j >> 3)] >> ((j & 7) << 2)) & 0xF;

    float s;
    if (mode == 0)      s = ((const float*)scales_raw)[(size_t)g * OUT_F + j];
    else if (mode == 1) s = dec_h(((const unsigned short*)scales_raw)[(size_t)g * OUT_F + j]);
    else                s = dec_b(((const unsigned short*)scales_raw)[(size_t)g * OUT_F + j]);
    const float zs = s * (float)z;

#pragma unroll
    for (int r = 0; r < 8; r++) {
        const int w = (q >> (r << 2)) & 0xF;
        g_W[(size_t)(i8 * 8 + r) * OUT_F + j] = __float2half(s * (float)w - zs);
    }
}

// ---------------------------------------------------------------------------
// Kernel 3: C = g_X @ g_W + bias. fp16 inputs, fp32 accum.
// 128x128x32 block tile, 8 warps (2x4), warp tile 64x32 (4x2 wmma frags).
// Epilogue stages fp32 through smem, adds bias, encodes per g_mode.
// ---------------------------------------------------------------------------
__global__ void __launch_bounds__(256)
gemm_bias_kernel(const void* __restrict__ bias_raw,
                 void* __restrict__ out_raw) {
    extern __shared__ __align__(32) unsigned char smem_raw[];
    __half* sA = reinterpret_cast<__half*>(smem_raw);
    __half* sB = sA + BM * LDA_S;
    float*  sC = reinterpret_cast<float*>(smem_raw);   // epilogue reuse

    const int mode = g_mode;
    const int tid    = threadIdx.x;
    const int wid    = tid >> 5;
    const int warp_m = wid >> 2;   // 0..1
    const int warp_n = wid & 3;    // 0..3

    const int m0 = blockIdx.y * BM;
    const int n0 = blockIdx.x * BN;

    wmma::fragment<wmma::accumulator, 16, 16, 16, float> acc[4][2];
#pragma unroll
    for (int i = 0; i < 4; i++)
#pragma unroll
        for (int j = 0; j < 2; j++)
            wmma::fill_fragment(acc[i][j], 0.0f);

    for (int k0 = 0; k0 < IN_F; k0 += BK) {
        // A tile: 128x32 halfs = 512 float4, 2 per thread
#pragma unroll
        for (int t = 0; t < 2; t++) {
            const int idx = tid + t * 256;
            const int row = idx >> 2;
            const int c8  = (idx & 3) << 3;
            const float4 v = *reinterpret_cast<const float4*>(
                g_X + (size_t)(m0 + row) * IN_F + k0 + c8);
            *reinterpret_cast<float4*>(sA + row * LDA_S + c8) = v;
        }
        // B tile: 32x128 halfs = 512 float4, 2 per thread
#pragma unroll
        for (int t = 0; t < 2; t++) {
            const int idx = tid + t * 256;
            const int row = idx >> 4;
            const int c8  = (idx & 15) << 3;
            const float4 v = *reinterpret_cast<const float4*>(
                g_W + (size_t)(k0 + row) * OUT_F + n0 + c8);
            *reinterpret_cast<float4*>(sB + row * LDB_S + c8) = v;
        }
        __syncthreads();

#pragma unroll
        for (int kk = 0; kk < BK; kk += 16) {
            wmma::fragment<wmma::matrix_b, 16, 16, 16, __half, wmma::row_major> bfrag[2];
#pragma unroll
            for (int j = 0; j < 2; j++)
                wmma::load_matrix_sync(bfrag[j],
                    sB + kk * LDB_S + warp_n * 32 + j * 16, LDB_S);
#pragma unroll
            for (int i = 0; i < 4; i++) {
                wmma::fragment<wmma::matrix_a, 16, 16, 16, __half, wmma::row_major> afrag;
                wmma::load_matrix_sync(afrag,
                    sA + (warp_m * 64 + i * 16) * LDA_S + kk, LDA_S);
#pragma unroll
                for (int j = 0; j < 2; j++)
                    wmma::mma_sync(acc[i][j], afrag, bfrag[j], acc[i][j]);
            }
        }
        __syncthreads();
    }

    // Epilogue
#pragma unroll
    for (int i = 0; i < 4; i++)
#pragma unroll
        for (int j = 0; j < 2; j++)
            wmma::store_matrix_sync(
                sC + (warp_m * 64 + i * 16) * LDC_S + warp_n * 32 + j * 16,
                acc[i][j], LDC_S, wmma::mem_row_major);
    __syncthreads();

    for (int idx = tid; idx < BM * (BN / 4); idx += 256) {
        const int row = idx / (BN / 4);
        const int c4  = (idx % (BN / 4)) * 4;
        const float4 v = *reinterpret_cast<const float4*>(sC + row * LDC_S + c4);
        const int gj = n0 + c4;
        float b0, b1, b2, b3;
        if (mode == 0) {
            const float4 b = *reinterpret_cast<const float4*>((const float*)bias_raw + gj);
            b0 = b.x; b1 = b.y; b2 = b.z; b3 = b.w;
        } else if (mode == 1) {
            const unsigned short* bb = (const unsigned short*)bias_raw;
            b0 = dec_h(bb[gj]); b1 = dec_h(bb[gj + 1]); b2 = dec_h(bb[gj + 2]); b3 = dec_h(bb[gj + 3]);
        } else {
            const unsigned short* bb = (const unsigned short*)bias_raw;
            b0 = dec_b(bb[gj]); b1 = dec_b(bb[gj + 1]); b2 = dec_b(bb[gj + 2]); b3 = dec_b(bb[gj + 3]);
        }
        const float r0 = v.x + b0, r1 = v.y + b1, r2 = v.z + b2, r3 = v.w + b3;
        const size_t off = (size_t)(m0 + row) * OUT_F + gj;
        if (mode == 0) {
            // round through fp16 to match the fp16 reference exactly
            float4 o;
            o.x = __half2float(__float2half(r0));
            o.y = __half2float(__float2half(r1));
            o.z = __half2float(__float2half(r2));
            o.w = __half2float(__float2half(r3));
            *reinterpret_cast<float4*>((float*)out_raw + off) = o;
        } else if (mode == 1) {
            uint2 p;
            p.x = (uint32_t)enc_h(r0) | ((uint32_t)enc_h(r1) << 16);
            p.y = (uint32_t)enc_h(r2) | ((uint32_t)enc_h(r3) << 16);
            *reinterpret_cast<uint2*>((unsigned short*)out_raw + off) = p;
        } else {
            uint2 p;
            p.x = (uint32_t)enc_b(r0) | ((uint32_t)enc_b(r1) << 16);
            p.y = (uint32_t)enc_b(r2) | ((uint32_t)enc_b(r3) << 16);
            *reinterpret_cast<uint2*>((unsigned short*)out_raw + off) = p;
        }
    }
}

// ---------------------------------------------------------------------------
// Launch. Inputs: x, qweight int32, qzeros int32, scales, bias. All 16-bit
// tensors may arrive widened to f32 (detected on device).
// ---------------------------------------------------------------------------
extern "C" void kernel_launch(void* const* d_in, const int* in_sizes, int n_in,
                              void* d_out, int out_size) {
    const void*    x       = d_in[0];
    const int32_t* qweight = (const int32_t*)d_in[1];
    const int32_t* qzeros  = (const int32_t*)d_in[2];
    const void*    scales  = d_in[3];
    const void*    bias    = d_in[4];

    detect_kernel<<<1, 1>>>(scales);

    const unsigned nchunks = (unsigned)((size_t)M_TOTAL * IN_F / 8);  // 4194304
    convert_x_kernel<<<nchunks / 256, 256>>>(x);

    dequant_kernel<<<dim3(OUT_F / 256, IN_F / 8), 256>>>(qweight, qzeros, scales);

    constexpr int SMEM_AB = (BM * LDA_S + BK * LDB_S) * (int)sizeof(__half);
    constexpr int SMEM_C  = BM * LDC_S * (int)sizeof(float);
    constexpr int SMEM    = (SMEM_C > SMEM_AB) ? SMEM_C : SMEM_AB;
    cudaFuncSetAttribute(gemm_bias_kernel,
                         cudaFuncAttributeMaxDynamicSharedMemorySize, SMEM);
    dim3 grid(OUT_F / BN, M_TOTAL / BM);
    gemm_bias_kernel<<<grid, 256, SMEM>>>(bias, d_out);
}

// round 5
// speedup vs baseline: 1.4343x; 1.4343x over previous
#include <cuda_runtime.h>
#include <cuda_fp16.h>
#include <cuda_bf16.h>
#include <cstdint>

// ---------------------------------------------------------------------------
// Problem constants
// ---------------------------------------------------------------------------
constexpr int IN_F    = 4096;    // K
constexpr int OUT_F   = 4096;    // N
constexpr int M_TOTAL = 8192;    // M

// GEMM tiling
constexpr int BM = 128, BN = 256, BK = 64;
constexpr int STAGES = 3;
constexpr int NSTG   = IN_F / BK;        // 64
constexpr int LDR    = 72;               // smem row stride in halfs (144B)
constexpr int A_BYTES     = BM * LDR * 2;            // 18432
constexpr int B_BYTES     = BN * LDR * 2;            // 36864
constexpr int STAGE_BYTES = A_BYTES + B_BYTES;       // 55296
constexpr int SMEM_TOTAL  = STAGES * STAGE_BYTES;    // 165888

// Scratch (__device__ globals = allowed scratch)
__device__ __half g_X [(size_t)M_TOTAL * IN_F];   // canonical fp16 x  (64MB)
__device__ __half g_Wt[(size_t)OUT_F * IN_F];     // dequant W^T [N,K] (32MB)
__device__ int    g_mode;                         // 0=f32, 1=fp16, 2=bf16 buffers

// ---------------------------------------------------------------------------
// helpers
// ---------------------------------------------------------------------------
__device__ __forceinline__ float dec_h(unsigned short v) {
    __half_raw h; h.x = v; return __half2float(__half(h));
}
__device__ __forceinline__ float dec_b(unsigned short v) {
    __nv_bfloat16_raw r; r.x = v; return __bfloat162float(__nv_bfloat16(r));
}
__device__ __forceinline__ unsigned short enc_h(float f) {
    __half h = __float2half(f); return reinterpret_cast<unsigned short&>(h);
}
__device__ __forceinline__ unsigned short enc_b(float f) {
    __nv_bfloat16 b = __float2bfloat16(f); return reinterpret_cast<unsigned short&>(b);
}
__device__ __forceinline__ void cp16(uint32_t saddr, const void* g) {
    asm volatile("cp.async.cg.shared.global [%0], [%1], 16;\n" :: "r"(saddr), "l"(g));
}
__device__ __forceinline__ void cp_commit() {
    asm volatile("cp.async.commit_group;\n" ::: "memory");
}
template <int N>
__device__ __forceinline__ void cp_wait() {
    asm volatile("cp.async.wait_group %0;\n" :: "n"(N) : "memory");
}
__device__ __forceinline__ void ldsm4(uint32_t* r, uint32_t addr) {
    asm volatile("ldmatrix.sync.aligned.m8n8.x4.shared.b16 {%0,%1,%2,%3}, [%4];\n"
                 : "=r"(r[0]), "=r"(r[1]), "=r"(r[2]), "=r"(r[3]) : "r"(addr));
}
__device__ __forceinline__ void mma16816(float* c, const uint32_t* a,
                                         uint32_t b0, uint32_t b1) {
    asm volatile(
        "mma.sync.aligned.m16n8k16.row.col.f32.f16.f16.f32 "
        "{%0,%1,%2,%3}, {%4,%5,%6,%7}, {%8,%9}, {%0,%1,%2,%3};\n"
        : "+f"(c[0]), "+f"(c[1]), "+f"(c[2]), "+f"(c[3])
        : "r"(a[0]), "r"(a[1]), "r"(a[2]), "r"(a[3]), "r"(b0), "r"(b1));
}

// ---------------------------------------------------------------------------
// Kernel 0: dtype probe on scales (true values in (0.001, 0.011]).
// ---------------------------------------------------------------------------
__global__ void detect_kernel(const void* scales) {
    const unsigned short* su = (const unsigned short*)scales;
    int c16 = 0, cbf = 0;
    for (int i = 0; i < 64; i++) {
        float vh = dec_h(su[i]); if (vh > 0.0005f && vh < 0.02f) c16++;
        float vb = dec_b(su[i]); if (vb > 0.0005f && vb < 0.02f) cbf++;
    }
    g_mode = (c16 >= 48) ? 1 : ((cbf >= 48) ? 2 : 0);
}

// ---------------------------------------------------------------------------
// Kernel 1: canonicalize x -> fp16 g_X (8 elems/thread)
// ---------------------------------------------------------------------------
__global__ void convert_x_kernel(const void* __restrict__ x_raw) {
    const int mode = g_mode;
    const size_t i8 = (size_t)blockIdx.x * blockDim.x + threadIdx.x;
    __half out[8];
    if (mode == 0) {
        const float4* xf = (const float4*)x_raw;
        const float4 a = xf[i8 * 2 + 0];
        const float4 b = xf[i8 * 2 + 1];
        out[0] = __float2half(a.x); out[1] = __float2half(a.y);
        out[2] = __float2half(a.z); out[3] = __float2half(a.w);
        out[4] = __float2half(b.x); out[5] = __float2half(b.y);
        out[6] = __float2half(b.z); out[7] = __float2half(b.w);
    } else {
        const uint4 v = ((const uint4*)x_raw)[i8];
        const unsigned int w[4] = {v.x, v.y, v.z, v.w};
        if (mode == 1) {
            *reinterpret_cast<uint4*>(out) = v;
        } else {
#pragma unroll
            for (int k = 0; k < 4; k++) {
                out[2*k+0] = __float2half(dec_b((unsigned short)(w[k] & 0xFFFF)));
                out[2*k+1] = __float2half(dec_b((unsigned short)(w[k] >> 16)));
            }
        }
    }
    *reinterpret_cast<uint4*>(&g_X[i8 * 8]) = *reinterpret_cast<const uint4*>(out);
}

// ---------------------------------------------------------------------------
// Kernel 2: dequantize 4-bit weights -> fp16 W^T [N, K] (K-major, coalesced)
// ---------------------------------------------------------------------------
__global__ void dequant_kernel(const int32_t* __restrict__ qweight,
                               const int32_t* __restrict__ qzeros,
                               const void* __restrict__ scales_raw) {
    const int mode = g_mode;
    const int tx = threadIdx.x;                  // 0..31
    const int ty = threadIdx.y;                  // 0..7
    const int j  = blockIdx.x * 8 + ty;          // N index
    const int i8 = blockIdx.y * 32 + tx;         // K/8 index
    const int g  = i8 >> 4;

    const uint32_t q = (uint32_t)qweight[(size_t)i8 * OUT_F + j];
    const int z = ((uint32_t)qzeros[(size_t)g * (OUT_F >> 3) + (j >> 3)] >> ((j & 7) << 2)) & 0xF;

    float s;
    if (mode == 0)      s = ((const float*)scales_raw)[(size_t)g * OUT_F + j];
    else if (mode == 1) s = dec_h(((const unsigned short*)scales_raw)[(size_t)g * OUT_F + j]);
    else                s = dec_b(((const unsigned short*)scales_raw)[(size_t)g * OUT_F + j]);
    const float zs = s * (float)z;

    __half out8[8];
#pragma unroll
    for (int r = 0; r < 8; r++) {
        const int w = (q >> (r << 2)) & 0xF;
        out8[r] = __float2half(s * (float)w - zs);
    }
    *reinterpret_cast<uint4*>(&g_Wt[(size_t)j * IN_F + i8 * 8]) =
        *reinterpret_cast<const uint4*>(out8);
}

// ---------------------------------------------------------------------------
// Kernel 3: GEMM via mma.sync.m16n8k16 + ldmatrix + 3-stage cp.async.
// CTA 128x256x64, 8 warps (2x4), warp tile 64x64.
// ---------------------------------------------------------------------------
__device__ __forceinline__ void load_stage(uint32_t sbase, int buf, int stage,
                                           int m0, int n0, int tid) {
    const int k0 = stage * BK;
    const uint32_t sA = sbase + buf * STAGE_BYTES;
    const uint32_t sB = sA + A_BYTES;
    // A: 128 rows x 8 segs of 16B -> 1024 chunks, 4/thread
#pragma unroll
    for (int t = 0; t < 4; t++) {
        const int idx = tid + t * 256;
        const int row = idx >> 3;
        const int seg = idx & 7;
        cp16(sA + row * (LDR * 2) + seg * 16,
             g_X + (size_t)(m0 + row) * IN_F + k0 + seg * 8);
    }
    // B: 256 rows x 8 segs -> 2048 chunks, 8/thread
#pragma unroll
    for (int t = 0; t < 8; t++) {
        const int idx = tid + t * 256;
        const int row = idx >> 3;
        const int seg = idx & 7;
        cp16(sB + row * (LDR * 2) + seg * 16,
             g_Wt + (size_t)(n0 + row) * IN_F + k0 + seg * 8);
    }
}

__global__ void __launch_bounds__(256, 1)
gemm_kernel(const void* __restrict__ bias_raw, void* __restrict__ out_raw) {
    extern __shared__ __align__(128) unsigned char smem[];
    const uint32_t sbase = (uint32_t)__cvta_generic_to_shared(smem);

    const int tid  = threadIdx.x;
    const int wid  = tid >> 5;
    const int lane = tid & 31;
    const int wm   = wid >> 2;            // 0..1
    const int wn   = wid & 3;             // 0..3
    const int mode = g_mode;

    const int m0 = blockIdx.x * BM;
    const int n0 = blockIdx.y * BN;

    // ldmatrix per-lane address components (byte offsets within a stage)
    const int l15  = lane & 15;
    const int lsel = (lane >> 4) * 16;
    const uint32_t a_off = (uint32_t)(wm * 64 + l15) * (LDR * 2) + lsel;            // in A region
    const uint32_t b_off = (uint32_t)A_BYTES + (uint32_t)(wn * 64 + l15) * (LDR * 2) + lsel;

    float acc[4][8][4];
#pragma unroll
    for (int i = 0; i < 4; i++)
#pragma unroll
        for (int j = 0; j < 8; j++)
#pragma unroll
            for (int k = 0; k < 4; k++) acc[i][j][k] = 0.0f;

    // prologue: stages 0,1
    load_stage(sbase, 0, 0, m0, n0, tid); cp_commit();
    load_stage(sbase, 1, 1, m0, n0, tid); cp_commit();

    for (int i = 0; i < NSTG; i++) {
        const int buf = i % STAGES;
        if (i == NSTG - 1) cp_wait<0>(); else cp_wait<1>();
        __syncthreads();

        const int ls = i + STAGES - 1;
        if (ls < NSTG) {
            load_stage(sbase, ls % STAGES, ls, m0, n0, tid);
            cp_commit();
        }

        const uint32_t st = sbase + buf * STAGE_BYTES;
#pragma unroll
        for (int kk = 0; kk < BK / 16; kk++) {
            uint32_t af[4][4], bf[4][4];
#pragma unroll
            for (int mi = 0; mi < 4; mi++)
                ldsm4(af[mi], st + a_off + mi * (16 * LDR * 2) + kk * 32);
#pragma unroll
            for (int nj = 0; nj < 4; nj++)
                ldsm4(bf[nj], st + b_off + nj * (16 * LDR * 2) + kk * 32);
#pragma unroll
            for (int mi = 0; mi < 4; mi++)
#pragma unroll
                for (int nj = 0; nj < 4; nj++) {
                    mma16816(acc[mi][nj * 2 + 0], af[mi], bf[nj][0], bf[nj][2]);
                    mma16816(acc[mi][nj * 2 + 1], af[mi], bf[nj][1], bf[nj][3]);
                }
        }
    }

    // ---- epilogue: direct register -> global with fused bias ----
    const int mrow = m0 + wm * 64 + (lane >> 2);
    const int ncol = n0 + wn * 64 + (lane & 3) * 2;

    float bl[8], bh[8];
#pragma unroll
    for (int j = 0; j < 8; j++) {
        const int c = ncol + j * 8;
        if (mode == 0) {
            bl[j] = ((const float*)bias_raw)[c];
            bh[j] = ((const float*)bias_raw)[c + 1];
        } else if (mode == 1) {
            bl[j] = dec_h(((const unsigned short*)bias_raw)[c]);
            bh[j] = dec_h(((const unsigned short*)bias_raw)[c + 1]);
        } else {
            bl[j] = dec_b(((const unsigned short*)bias_raw)[c]);
            bh[j] = dec_b(((const unsigned short*)bias_raw)[c + 1]);
        }
    }

#pragma unroll
    for (int mi = 0; mi < 4; mi++) {
        const int r0 = mrow + mi * 16;
#pragma unroll
        for (int j = 0; j < 8; j++) {
            const int c = ncol + j * 8;
            const float v0 = acc[mi][j][0] + bl[j];
            const float v1 = acc[mi][j][1] + bh[j];
            const float v2 = acc[mi][j][2] + bl[j];
            const float v3 = acc[mi][j][3] + bh[j];
            if (mode == 0) {
                float2 p0, p1;
                p0.x = __half2float(__float2half(v0));
                p0.y = __half2float(__float2half(v1));
                p1.x = __half2float(__float2half(v2));
                p1.y = __half2float(__float2half(v3));
                *reinterpret_cast<float2*>((float*)out_raw + (size_t)r0 * OUT_F + c) = p0;
                *reinterpret_cast<float2*>((float*)out_raw + (size_t)(r0 + 8) * OUT_F + c) = p1;
            } else if (mode == 1) {
                uint32_t p0 = (uint32_t)enc_h(v0) | ((uint32_t)enc_h(v1) << 16);
                uint32_t p1 = (uint32_t)enc_h(v2) | ((uint32_t)enc_h(v3) << 16);
                *reinterpret_cast<uint32_t*>((unsigned short*)out_raw + (size_t)r0 * OUT_F + c) = p0;
                *reinterpret_cast<uint32_t*>((unsigned short*)out_raw + (size_t)(r0 + 8) * OUT_F + c) = p1;
            } else {
                uint32_t p0 = (uint32_t)enc_b(v0) | ((uint32_t)enc_b(v1) << 16);
                uint32_t p1 = (uint32_t)enc_b(v2) | ((uint32_t)enc_b(v3) << 16);
                *reinterpret_cast<uint32_t*>((unsigned short*)out_raw + (size_t)r0 * OUT_F + c) = p0;
                *reinterpret_cast<uint32_t*>((unsigned short*)out_raw + (size_t)(r0 + 8) * OUT_F + c) = p1;
            }
        }
    }
}

// ---------------------------------------------------------------------------
// Launch
// ---------------------------------------------------------------------------
extern "C" void kernel_launch(void* const* d_in, const int* in_sizes, int n_in,
                              void* d_out, int out_size) {
    const void*    x       = d_in[0];
    const int32_t* qweight = (const int32_t*)d_in[1];
    const int32_t* qzeros  = (const int32_t*)d_in[2];
    const void*    scales  = d_in[3];
    const void*    bias    = d_in[4];

    detect_kernel<<<1, 1>>>(scales);

    const unsigned nchunks = (unsigned)((size_t)M_TOTAL * IN_F / 8);
    convert_x_kernel<<<nchunks / 256, 256>>>(x);

    dequant_kernel<<<dim3(OUT_F / 8, IN_F / 256), dim3(32, 8)>>>(qweight, qzeros, scales);

    cudaFuncSetAttribute(gemm_kernel,
                         cudaFuncAttributeMaxDynamicSharedMemorySize, SMEM_TOTAL);
    dim3 grid(M_TOTAL / BM, OUT_F / BN);    // (64, 16)
    gemm_kernel<<<grid, 256, SMEM_TOTAL>>>(bias, d_out);
}